// round 1
// baseline (speedup 1.0000x reference)
#include <cuda_runtime.h>
#include <cuda_bf16.h>
#include <math.h>

// Problem constants
#define BATCH 2
#define T_LEN 2048
#define D_MODEL 2048
#define NH 16
#define NKV 4
#define HD 128
#define EPS 1e-6f

// ---------------- scratch (device globals; no allocation allowed) ----------
__device__ float g_q[BATCH * T_LEN * NH * HD];    // [b,t,h,d]   33.5 MB
__device__ float g_k[BATCH * T_LEN * NKV * HD];   // [b,t,kv,d]   8.4 MB
__device__ float g_v[BATCH * T_LEN * NKV * HD];   //              8.4 MB
__device__ float g_att[BATCH * T_LEN * NH * HD];  // [b,t,h*d]   33.5 MB

// ---------------- 128x128x16 fp32 tiled GEMM: C = A[MxK] @ B[KxN] ----------
__global__ __launch_bounds__(256) void sgemm128(
    const float* __restrict__ A, const float* __restrict__ B,
    float* __restrict__ C, int M, int N, int K)
{
    __shared__ float As[16][132];   // transposed A tile, padded
    __shared__ float Bs[16][128];

    const int tid = threadIdx.x;
    const int bm = blockIdx.y * 128;
    const int bn = blockIdx.x * 128;
    const int tr8 = (tid >> 4) * 8;
    const int tc8 = (tid & 15) * 8;

    float acc[8][8];
#pragma unroll
    for (int i = 0; i < 8; i++)
#pragma unroll
        for (int j = 0; j < 8; j++) acc[i][j] = 0.f;

    for (int k0 = 0; k0 < K; k0 += 16) {
#pragma unroll
        for (int l = 0; l < 2; l++) {
            int id = l * 256 + tid;
            int ar = id >> 2, ac = (id & 3) << 2;
            float4 av = *(const float4*)&A[(size_t)(bm + ar) * K + k0 + ac];
            As[ac + 0][ar] = av.x; As[ac + 1][ar] = av.y;
            As[ac + 2][ar] = av.z; As[ac + 3][ar] = av.w;
            int br = id >> 5, bc = (id & 31) << 2;
            *(float4*)&Bs[br][bc] =
                *(const float4*)&B[(size_t)(k0 + br) * N + bn + bc];
        }
        __syncthreads();
#pragma unroll
        for (int k = 0; k < 16; k++) {
            float a[8], b[8];
            *(float4*)&a[0] = *(float4*)&As[k][tr8];
            *(float4*)&a[4] = *(float4*)&As[k][tr8 + 4];
            *(float4*)&b[0] = *(float4*)&Bs[k][tc8];
            *(float4*)&b[4] = *(float4*)&Bs[k][tc8 + 4];
#pragma unroll
            for (int i = 0; i < 8; i++)
#pragma unroll
                for (int j = 0; j < 8; j++)
                    acc[i][j] = fmaf(a[i], b[j], acc[i][j]);
        }
        __syncthreads();
    }
#pragma unroll
    for (int i = 0; i < 8; i++) {
        float4* cp = (float4*)&C[(size_t)(bm + tr8 + i) * N + bn + tc8];
        cp[0] = make_float4(acc[i][0], acc[i][1], acc[i][2], acc[i][3]);
        cp[1] = make_float4(acc[i][4], acc[i][5], acc[i][6], acc[i][7]);
    }
}

// ---------------- fused RMSNorm (over HD) + interleaved RoPE ----------------
// one block (128 threads) per row (b,t,head); heads = NH or NKV
__global__ __launch_bounds__(128) void rmsnorm_rope(
    float* __restrict__ x, const float* __restrict__ scale,
    const float* __restrict__ cosT, const float* __restrict__ sinT, int heads)
{
    const int row = blockIdx.x;
    const int t = (row / heads) % T_LEN;
    const int d = threadIdx.x;

    float v = x[(size_t)row * HD + d];
    float ss = v * v;
#pragma unroll
    for (int m = 16; m > 0; m >>= 1)
        ss += __shfl_xor_sync(0xffffffffu, ss, m);
    __shared__ float wsum[4];
    if ((d & 31) == 0) wsum[d >> 5] = ss;
    __syncthreads();
    float tot = wsum[0] + wsum[1] + wsum[2] + wsum[3];
    float r = rsqrtf(tot * (1.0f / HD) + EPS);

    float xn = v * r * scale[d];
    float part = __shfl_xor_sync(0xffffffffu, xn, 1);  // pair partner
    float rot = (d & 1) ? part : -part;                // even: -x[d+1], odd: x[d-1]
    x[(size_t)row * HD + d] = xn * cosT[t * HD + d] + rot * sinT[t * HD + d];
}

// ---------------- causal GQA flash attention (fp32) -------------------------
// grid (T/64, NH, B), 256 threads. BQ = BK = 64, HD = 128.
#define KPAD 68
__global__ __launch_bounds__(256) void flash_attn(
    const float* __restrict__ q, const float* __restrict__ k,
    const float* __restrict__ v, float* __restrict__ o)
{
    extern __shared__ float sm[];
    float* Qs = sm;                    // [64][128]
    float* Ks = Qs + 64 * 128;         // [128][KPAD] transposed
    float* Vs = Ks + 128 * KPAD;       // [64][128]
    float* Ps = Vs + 64 * 128;         // [64][64]

    const int qt = blockIdx.x, h = blockIdx.y, b = blockIdx.z;
    const int tid = threadIdx.x;
    const int kvh = h >> 2;            // NH/NKV = 4 groups
    const int sr = (tid >> 4) * 4;     // 4 rows owned (same for S and O phases)
    const int sc = (tid & 15) * 4;     // 4 score cols
    const int oc = (tid & 15) * 8;     // 8 output cols
    const float qk_scale = 0.08838834764831845f;  // 1/sqrt(128)

    // load Q tile (pre-scaled)
    const int q0 = ((b * T_LEN + qt * 64) * NH + h) * HD;
    for (int idx = tid; idx < 64 * 128; idx += 256) {
        int r = idx >> 7, c = idx & 127;
        Qs[r * 128 + c] = q[q0 + r * NH * HD + c] * qk_scale;
    }

    float m_i[4], l_i[4], Oacc[4][8];
#pragma unroll
    for (int i = 0; i < 4; i++) {
        m_i[i] = -1e30f; l_i[i] = 0.f;
#pragma unroll
        for (int j = 0; j < 8; j++) Oacc[i][j] = 0.f;
    }

    for (int kt = 0; kt <= qt; kt++) {
        const int kb = ((b * T_LEN + kt * 64) * NKV + kvh) * HD;
        for (int idx = tid; idx < 64 * 128; idx += 256) {
            int r = idx >> 7, c = idx & 127;
            Ks[c * KPAD + r] = k[kb + r * NKV * HD + c];
            Vs[idx]          = v[kb + r * NKV * HD + c];
        }
        __syncthreads();

        // S = Qs @ Ks^T (4x4 per thread)
        float s[4][4];
#pragma unroll
        for (int i = 0; i < 4; i++)
#pragma unroll
            for (int j = 0; j < 4; j++) s[i][j] = 0.f;
#pragma unroll 8
        for (int kk = 0; kk < 128; kk++) {
            float4 bb = *(float4*)&Ks[kk * KPAD + sc];
#pragma unroll
            for (int i = 0; i < 4; i++) {
                float a = Qs[(sr + i) * 128 + kk];
                s[i][0] = fmaf(a, bb.x, s[i][0]);
                s[i][1] = fmaf(a, bb.y, s[i][1]);
                s[i][2] = fmaf(a, bb.z, s[i][2]);
                s[i][3] = fmaf(a, bb.w, s[i][3]);
            }
        }
        if (kt == qt) {  // diagonal tile: mask col > row
#pragma unroll
            for (int i = 0; i < 4; i++)
#pragma unroll
                for (int j = 0; j < 4; j++)
                    if (sc + j > sr + i) s[i][j] = -1e30f;
        }

        // online softmax (16 lanes per row-group hold identical reductions)
        float alpha[4];
#pragma unroll
        for (int i = 0; i < 4; i++) {
            float mx = fmaxf(fmaxf(s[i][0], s[i][1]), fmaxf(s[i][2], s[i][3]));
#pragma unroll
            for (int m = 8; m > 0; m >>= 1)
                mx = fmaxf(mx, __shfl_xor_sync(0xffffffffu, mx, m));
            float mnew = fmaxf(m_i[i], mx);
            alpha[i] = __expf(m_i[i] - mnew);
            m_i[i] = mnew;
            float rs = 0.f;
#pragma unroll
            for (int j = 0; j < 4; j++) {
                s[i][j] = __expf(s[i][j] - mnew);
                rs += s[i][j];
            }
#pragma unroll
            for (int m = 8; m > 0; m >>= 1)
                rs += __shfl_xor_sync(0xffffffffu, rs, m);
            l_i[i] = l_i[i] * alpha[i] + rs;
            *(float4*)&Ps[(sr + i) * 64 + sc] =
                make_float4(s[i][0], s[i][1], s[i][2], s[i][3]);
        }
#pragma unroll
        for (int i = 0; i < 4; i++)
#pragma unroll
            for (int j = 0; j < 8; j++) Oacc[i][j] *= alpha[i];
        __syncthreads();

        // O += P @ V
#pragma unroll 4
        for (int kc = 0; kc < 64; kc++) {
            float4 b0 = *(float4*)&Vs[kc * 128 + oc];
            float4 b1 = *(float4*)&Vs[kc * 128 + oc + 4];
#pragma unroll
            for (int i = 0; i < 4; i++) {
                float a = Ps[(sr + i) * 64 + kc];
                Oacc[i][0] = fmaf(a, b0.x, Oacc[i][0]);
                Oacc[i][1] = fmaf(a, b0.y, Oacc[i][1]);
                Oacc[i][2] = fmaf(a, b0.z, Oacc[i][2]);
                Oacc[i][3] = fmaf(a, b0.w, Oacc[i][3]);
                Oacc[i][4] = fmaf(a, b1.x, Oacc[i][4]);
                Oacc[i][5] = fmaf(a, b1.y, Oacc[i][5]);
                Oacc[i][6] = fmaf(a, b1.z, Oacc[i][6]);
                Oacc[i][7] = fmaf(a, b1.w, Oacc[i][7]);
            }
        }
        __syncthreads();
    }

    // normalize and write [b, t, h, d]
#pragma unroll
    for (int i = 0; i < 4; i++) {
        float inv = 1.f / l_i[i];
        size_t ob = ((size_t)(b * T_LEN + qt * 64 + sr + i) * NH + h) * HD + oc;
        *(float4*)&o[ob] = make_float4(Oacc[i][0] * inv, Oacc[i][1] * inv,
                                       Oacc[i][2] * inv, Oacc[i][3] * inv);
        *(float4*)&o[ob + 4] = make_float4(Oacc[i][4] * inv, Oacc[i][5] * inv,
                                           Oacc[i][6] * inv, Oacc[i][7] * inv);
    }
}

// ---------------- launcher ---------------------------------------------------
extern "C" void kernel_launch(void* const* d_in, const int* in_sizes, int n_in,
                              void* d_out, int out_size)
{
    const float* x       = (const float*)d_in[0];
    const float* Wq      = (const float*)d_in[1];
    const float* Wk      = (const float*)d_in[2];
    const float* Wv      = (const float*)d_in[3];
    const float* Wo      = (const float*)d_in[4];
    const float* q_scale = (const float*)d_in[5];
    const float* k_scale = (const float*)d_in[6];
    const float* cosT    = (const float*)d_in[7];
    const float* sinT    = (const float*)d_in[8];
    float* out = (float*)d_out;

    float *pq, *pk, *pv, *patt;
    cudaGetSymbolAddress((void**)&pq,   g_q);
    cudaGetSymbolAddress((void**)&pk,   g_k);
    cudaGetSymbolAddress((void**)&pv,   g_v);
    cudaGetSymbolAddress((void**)&patt, g_att);

    const int M = BATCH * T_LEN;  // 4096

    // QKV projections
    sgemm128<<<dim3(NH * HD / 128, M / 128), 256>>>(x, Wq, pq, M, NH * HD, D_MODEL);
    sgemm128<<<dim3(NKV * HD / 128, M / 128), 256>>>(x, Wk, pk, M, NKV * HD, D_MODEL);
    sgemm128<<<dim3(NKV * HD / 128, M / 128), 256>>>(x, Wv, pv, M, NKV * HD, D_MODEL);

    // RMSNorm + RoPE on q and k
    rmsnorm_rope<<<M * NH, 128>>>(pq, q_scale, cosT, sinT, NH);
    rmsnorm_rope<<<M * NKV, 128>>>(pk, k_scale, cosT, sinT, NKV);

    // flash attention
    const int smem = (64 * 128 + 128 * KPAD + 64 * 128 + 64 * 64) * sizeof(float);
    static bool attr_set = false;
    if (!attr_set) {
        cudaFuncSetAttribute(flash_attn, cudaFuncAttributeMaxDynamicSharedMemorySize, smem);
        attr_set = true;
    }
    flash_attn<<<dim3(T_LEN / 64, NH, BATCH), 256, smem>>>(pq, pk, pv, patt);

    // output projection
    sgemm128<<<dim3(D_MODEL / 128, M / 128), 256>>>(patt, Wo, out, M, D_MODEL, D_MODEL);
}